// round 8
// baseline (speedup 1.0000x reference)
#include <cuda_runtime.h>
#include <cuda_fp16.h>
#include <cstdint>

#define NN   100000
#define EE   300000
#define ETOT 400000   // EE + NN self loops
#define GG   4000
#define INC  9
#define HIDC 128
#define NH   4
#define HC1  512      // NH*HIDC

typedef unsigned long long ull;

// ---------------- scratch (device globals; no allocation allowed) ----------------
__device__ float g_h2  [(size_t)NN * HIDC];  // 51 MB
__device__ float g_act2[(size_t)NN * HIDC];  // 51 MB
__device__ float g_xagg[(size_t)NN * NH * INC]; // 14.4 MB
__device__ float g_x12 [(size_t)NN * 12];    // 4.8 MB padded x
__device__ float g_as1[NN * NH], g_ad1[NN * NH];
__device__ float g_as2[NN],      g_ad2[NN];
__device__ float g_asv[NH * INC], g_adv[NH * INC];
__device__ int   g_deg[NN];
__device__ int   g_rowoff[NN + 1];
__device__ int   g_cursor[NN];
__device__ int   g_csrc[ETOT];
__device__ int   g_blk[128];
__device__ float g_cnt[GG];
// W2 fp16 image, row-major [head][k(128)][n(128)]
__device__ unsigned short g_BimgF[NH][HIDC * HIDC];

__device__ __forceinline__ float lrelu(float x) { return x > 0.f ? x : 0.2f * x; }

// FMA-only exp: e^x = 2^i * 2^f. Degree-5 poly on f in [0,1). No MUFU.
__device__ __forceinline__ float fexp(float x) {
    float t = x * 1.4426950408889634f;
    float fi = floorf(t);
    float f = t - fi;
    float p = 0.0013298820f;
    p = fmaf(p, f, 0.0096180635f);
    p = fmaf(p, f, 0.0555041087f);
    p = fmaf(p, f, 0.2402265070f);
    p = fmaf(p, f, 0.6931471806f);
    p = fmaf(p, f, 1.0f);
    int ei = (int)fi;
    ei = ei < -126 ? -126 : (ei > 126 ? 126 : ei);
    float s = __int_as_float((ei + 127) << 23);
    return p * s;
}
__device__ __forceinline__ float eluf(float x) { return x > 0.f ? x : (fexp(x) - 1.f); }

__device__ __forceinline__ uint32_t smem_u32(const void* p) {
    uint32_t a;
    asm("{ .reg .u64 t; cvta.to.shared.u64 t, %1; cvt.u32.u64 %0, t; }" : "=r"(a) : "l"(p));
    return a;
}
__device__ __forceinline__ void ldsm_x4(uint32_t* r, uint32_t addr) {
    asm volatile("ldmatrix.sync.aligned.m8n8.x4.shared.b16 {%0,%1,%2,%3}, [%4];"
        : "=r"(r[0]), "=r"(r[1]), "=r"(r[2]), "=r"(r[3]) : "r"(addr));
}
__device__ __forceinline__ void ldsm_x4_t(uint32_t* r, uint32_t addr) {
    asm volatile("ldmatrix.sync.aligned.m8n8.x4.trans.shared.b16 {%0,%1,%2,%3}, [%4];"
        : "=r"(r[0]), "=r"(r[1]), "=r"(r[2]), "=r"(r[3]) : "r"(addr));
}
__device__ __forceinline__ void mma16816h(float* c, const uint32_t* a, const uint32_t* b) {
    asm volatile("mma.sync.aligned.m16n8k16.row.col.f32.f16.f16.f32 "
        "{%0,%1,%2,%3}, {%4,%5,%6,%7}, {%8,%9}, {%0,%1,%2,%3};"
        : "+f"(c[0]), "+f"(c[1]), "+f"(c[2]), "+f"(c[3])
        : "r"(a[0]), "r"(a[1]), "r"(a[2]), "r"(a[3]), "r"(b[0]), "r"(b[1]));
}
#define CP_ASYNC16(dst, src) asm volatile("cp.async.cg.shared.global [%0], [%1], 16;" :: "r"(dst), "l"(src))
#define CP_COMMIT()          asm volatile("cp.async.commit_group;" ::: "memory")
#define CP_WAIT0()           asm volatile("cp.async.wait_group 0;" ::: "memory")

// ---------------- 0: prep = zero + pad x + W2 fp16 image + attention prevec ----------------
__global__ void k_prep(float* __restrict__ out, const float* __restrict__ x,
                       const float* __restrict__ W2, const float* __restrict__ W1,
                       const float* __restrict__ a_src1, const float* __restrict__ a_dst1) {
    int i = blockIdx.x * blockDim.x + threadIdx.x;
    if (i < GG * HIDC) out[i] = 0.f;
    if (i < NN)        g_deg[i] = 0;
    if (i < GG)        g_cnt[i] = 0.f;
    if (i < NN * 12) {
        int r = i / 12, c = i - r * 12;
        g_x12[i] = (c < INC) ? x[r * INC + c] : 0.f;
    }
    if (i < NH * HIDC * HIDC) {
        __half v = __float2half_rn(W2[i]);
        ((unsigned short*)g_BimgF)[i] = *(unsigned short*)&v;
    }
    if (i < NH * INC) {
        int h = i / INC, k = i % INC;
        float s = 0.f, d = 0.f;
        const float* wrow = W1 + k * HC1 + h * HIDC;
        const float* as = a_src1 + h * HIDC;
        const float* ad = a_dst1 + h * HIDC;
        for (int c = 0; c < HIDC; c++) { float w = wrow[c]; s += w * as[c]; d += w * ad[c]; }
        g_asv[i] = s; g_adv[i] = d;
    }
}

// ---------------- 1: dst histogram ----------------
__global__ void k_hist(const int* __restrict__ ei) {
    int i = blockIdx.x * blockDim.x + threadIdx.x;
    if (i >= ETOT) return;
    int d = (i < EE) ? ei[EE + i] : (i - EE);
    atomicAdd(&g_deg[d], 1);
}

// ---------------- 2a: per-block inclusive scan + block totals ----------------
__global__ void k_scanA() {
    __shared__ int sh[1024];
    int t = threadIdx.x;
    int i = blockIdx.x * 1024 + t;
    int v = (i < NN) ? g_deg[i] : 0;
    sh[t] = v; __syncthreads();
#pragma unroll
    for (int o = 1; o < 1024; o <<= 1) {
        int u = (t >= o) ? sh[t - o] : 0;
        __syncthreads();
        sh[t] += u;
        __syncthreads();
    }
    if (i < NN) g_rowoff[i] = sh[t] - v;     // exclusive within block
    if (t == 1023) g_blk[blockIdx.x] = sh[1023];
}

// ---------------- 2b: scan the 98 block totals ----------------
__global__ void k_scanB() {
    __shared__ int sh[128];
    int t = threadIdx.x;
    int v = (t < 98) ? g_blk[t] : 0;
    sh[t] = v; __syncthreads();
#pragma unroll
    for (int o = 1; o < 128; o <<= 1) {
        int u = (t >= o) ? sh[t - o] : 0;
        __syncthreads();
        sh[t] += u;
        __syncthreads();
    }
    if (t < 98) g_blk[t] = sh[t] - v;        // exclusive block offset
}

// ---------------- 2c: add offsets, init cursors ----------------
__global__ void k_scanC() {
    int i = blockIdx.x * 1024 + threadIdx.x;
    if (i < NN) {
        int r = g_rowoff[i] + g_blk[blockIdx.x];
        g_rowoff[i] = r;
        g_cursor[i] = r;
    }
    if (i == 0) g_rowoff[NN] = ETOT;
}

// ---------------- 3: scatter into CSR ----------------
__global__ void k_scatter(const int* __restrict__ ei) {
    int i = blockIdx.x * blockDim.x + threadIdx.x;
    if (i >= ETOT) return;
    int s, d;
    if (i < EE) { s = ei[i]; d = ei[EE + i]; } else { s = d = i - EE; }
    int pos = atomicAdd(&g_cursor[d], 1);
    g_csrc[pos] = s;
}

// ---------------- 5: per-node attention scalars (layer 1) ----------------
__global__ void k_alpha1(const float* __restrict__ x) {
    int n = blockIdx.x * blockDim.x + threadIdx.x;
    if (n >= NN) return;
    float xr[INC];
#pragma unroll
    for (int k = 0; k < INC; k++) xr[k] = x[n * INC + k];
    float sv[NH], dv[NH];
#pragma unroll
    for (int h = 0; h < NH; h++) {
        float a = 0.f, b = 0.f;
#pragma unroll
        for (int k = 0; k < INC; k++) { a += xr[k] * g_asv[h * INC + k]; b += xr[k] * g_adv[h * INC + k]; }
        sv[h] = a; dv[h] = b;
    }
    *(float4*)&g_as1[n * 4] = make_float4(sv[0], sv[1], sv[2], sv[3]);
    *(float4*)&g_ad1[n * 4] = make_float4(dv[0], dv[1], dv[2], dv[3]);
}

// ---------------- 6: layer-1 aggregation, single pass ----------
__global__ void k_agg1() {
    int v = blockIdx.x * blockDim.x + threadIdx.x;
    if (v >= NN) return;
    int e0 = g_rowoff[v], e1 = g_rowoff[v + 1];
    float4 adv = *(const float4*)&g_ad1[v * 4];
    float z[NH] = {0.f, 0.f, 0.f, 0.f};
    float acc[NH][INC];
#pragma unroll
    for (int h = 0; h < NH; h++)
#pragma unroll
        for (int k = 0; k < INC; k++) acc[h][k] = 0.f;
    for (int e = e0; e < e1; e++) {
        int s = g_csrc[e];
        float4 as = *(const float4*)&g_as1[s * 4];
        float w[NH];
        w[0] = fexp(lrelu(as.x + adv.x));
        w[1] = fexp(lrelu(as.y + adv.y));
        w[2] = fexp(lrelu(as.z + adv.z));
        w[3] = fexp(lrelu(as.w + adv.w));
        z[0] += w[0]; z[1] += w[1]; z[2] += w[2]; z[3] += w[3];
        const float4* xp = (const float4*)&g_x12[(size_t)s * 12];
        float4 x0 = __ldg(xp), x1 = __ldg(xp + 1), x2 = __ldg(xp + 2);
        float xv[INC] = {x0.x, x0.y, x0.z, x0.w, x1.x, x1.y, x1.z, x1.w, x2.x};
#pragma unroll
        for (int h = 0; h < NH; h++)
#pragma unroll
            for (int k = 0; k < INC; k++) acc[h][k] += w[h] * xv[k];
    }
#pragma unroll
    for (int h = 0; h < NH; h++) {
        float inv = 1.f / (z[h] + 1e-16f);
#pragma unroll
        for (int k = 0; k < INC; k++) g_xagg[(size_t)v * 36 + h * INC + k] = acc[h][k] * inv;
    }
}

// ---------------- 7: FUSED  h2 = (elu(xagg@W1+b1)) @ W2 : fp16 HMMA, 2 blocks/SM ---
#define TP 136                          // padded row length (elements)
#define TILE_HB (128 * TP * 2)          // 34816 bytes (A or B)
#define FUSED_DYN_SMEM (2 * TILE_HB)    // 69632

__global__ __launch_bounds__(256, 2) void k_fused_mma(const float* __restrict__ W1,
                                                      const float* __restrict__ b1,
                                                      const float* __restrict__ a_src2,
                                                      const float* __restrict__ a_dst2) {
    extern __shared__ char dyn[];
    char* sA = dyn;
    char* sB = dyn + TILE_HB;

    __shared__ float sX[128 * 9];
    __shared__ float sU[9 * 128];
    __shared__ float sBias[128];
    __shared__ float sAv[128], sDv[128];

    int tid = threadIdx.x;
    int wid = tid >> 5;
    int lane = tid & 31;
    int bm = blockIdx.x * 128;
    int wm = (wid & 3) * 32;
    int wn = (wid >> 2) * 64;

    uint32_t aS = smem_u32(sA), bS = smem_u32(sB);

    if (tid < 128) { sAv[tid] = a_src2[tid]; sDv[tid] = a_dst2[tid]; }

    float acc[2][8][4];
#pragma unroll
    for (int t = 0; t < 2; t++)
#pragma unroll
        for (int j = 0; j < 8; j++)
#pragma unroll
            for (int q = 0; q < 4; q++) acc[t][j][q] = 0.f;

    for (int h = 0; h < NH; h++) {
        __syncthreads();   // previous MMA done; tiles free
        // ---- cp.async B(h) ----
        {
            int base = tid * 8;
#pragma unroll
            for (int i = 0; i < 8; i++) {
                int idx = base + i;
                int k = idx >> 4, n8 = idx & 15;
                uint32_t dst = bS + (uint32_t)k * (TP * 2) + (uint32_t)n8 * 16;
                const char* src = (const char*)&g_BimgF[h][0] + ((size_t)k * 128 + n8 * 8) * 2;
                CP_ASYNC16(dst, src);
            }
            CP_COMMIT();
        }
        // ---- stage xagg, W1 slice, bias ----
        for (int idx = tid; idx < 128 * 9; idx += 256) {
            int row = idx / 9, k = idx - row * 9;
            int n = bm + row;
            sX[idx] = (n < NN) ? g_xagg[(size_t)n * 36 + h * 9 + k] : 0.f;
        }
        for (int idx = tid; idx < 9 * 128; idx += 256) sU[idx] = W1[(idx >> 7) * HC1 + h * HIDC + (idx & 127)];
        if (tid < 128) sBias[tid] = b1[h * HIDC + tid];
        __syncthreads();   // sX/sU ready
        // ---- compute act1 chunk -> fp16 tile (FMA-only elu) ----
        {
            int p = tid & 63;
            int kk0 = 2 * p, kk1 = kk0 + 1;
            int rg = tid >> 6;
            float w0[9], w1[9];
#pragma unroll
            for (int k = 0; k < 9; k++) { w0[k] = sU[k * 128 + kk0]; w1[k] = sU[k * 128 + kk1]; }
            float bb0 = sBias[kk0], bb1 = sBias[kk1];
#pragma unroll 4
            for (int i = 0; i < 32; i++) {
                int row = rg * 32 + i;
                const float* xr = &sX[row * 9];
                float a0 = bb0, a1 = bb1;
#pragma unroll
                for (int k = 0; k < 9; k++) { float xv = xr[k]; a0 += xv * w0[k]; a1 += xv * w1[k]; }
                a0 = eluf(a0);
                a1 = eluf(a1);
                __half h0 = __float2half_rn(a0);
                __half h1 = __float2half_rn(a1);
                uint32_t hv = ((uint32_t)*(unsigned short*)&h1 << 16) | *(unsigned short*)&h0;
                *(uint32_t*)(sA + (uint32_t)row * (TP * 2) + (uint32_t)kk0 * 2) = hv;
            }
        }
        CP_WAIT0();
        __syncthreads();   // sA + sB ready
        // ---- HMMA: 8 k-steps ----
#pragma unroll
        for (int ks = 0; ks < 8; ks++) {
            int k0 = ks * 16;
            uint32_t ah[2][4], bh[16];
            {
                uint32_t rowb = (uint32_t)(wm + (lane & 15)) * (TP * 2)
                              + (uint32_t)(k0 + ((lane >> 4) << 3)) * 2;
                ldsm_x4(ah[0], aS + rowb);
                ldsm_x4(ah[1], aS + rowb + 16u * (TP * 2));
            }
#pragma unroll
            for (int g = 0; g < 4; g++) {
                uint32_t off = (uint32_t)(k0 + (lane & 15)) * (TP * 2)
                             + (uint32_t)(wn + 16 * g + ((lane >> 4) << 3)) * 2;
                ldsm_x4_t(&bh[4 * g], bS + off);
            }
#pragma unroll
            for (int t = 0; t < 2; t++)
#pragma unroll
                for (int j = 0; j < 8; j++)
                    mma16816h(acc[t][j], ah[t], &bh[2 * j]);
        }
    }

    // ---- epilogue: store h2, fused layer-2 attention scalars ----
    __syncthreads();
    float* sPs = sX;
    float* sPd = sX + 128;
    if (tid < 128) { sPs[tid] = 0.f; sPd[tid] = 0.f; }
    __syncthreads();
#pragma unroll
    for (int t = 0; t < 2; t++)
#pragma unroll
        for (int rh = 0; rh < 2; rh++) {
            int rl = wm + t * 16 + (lane >> 2) + rh * 8;
            int row = bm + rl;
            float ps = 0.f, pd = 0.f;
#pragma unroll
            for (int j = 0; j < 8; j++) {
                float c0 = acc[t][j][rh * 2 + 0];
                float c1 = acc[t][j][rh * 2 + 1];
                int col = wn + 8 * j + (lane & 3) * 2;
                ps += c0 * sAv[col] + c1 * sAv[col + 1];
                pd += c0 * sDv[col] + c1 * sDv[col + 1];
                if (row < NN) {
                    *(float2*)&g_h2[(size_t)row * HIDC + col] = make_float2(c0, c1);
                }
            }
            ps += __shfl_xor_sync(0xffffffffu, ps, 1);
            ps += __shfl_xor_sync(0xffffffffu, ps, 2);
            pd += __shfl_xor_sync(0xffffffffu, pd, 1);
            pd += __shfl_xor_sync(0xffffffffu, pd, 2);
            if ((lane & 3) == 0) {
                atomicAdd(&sPs[rl], ps);
                atomicAdd(&sPd[rl], pd);
            }
        }
    __syncthreads();
    if (tid < 128) {
        int row = bm + tid;
        if (row < NN) { g_as2[row] = sPs[tid]; g_ad2[row] = sPd[tid]; }
    }
}

// ---------------- 10: layer-2 aggregation, single pass (warp per node) ----------------
__global__ void k_agg2(const float* __restrict__ b2) {
    int v = (blockIdx.x * blockDim.x + threadIdx.x) >> 5;
    int lane = threadIdx.x & 31;
    if (v >= NN) return;
    int e0 = g_rowoff[v], e1 = g_rowoff[v + 1];
    float ad = g_ad2[v];
    float z = 0.f;
    float4 acc = make_float4(0.f, 0.f, 0.f, 0.f);
    for (int e = e0; e < e1; e++) {
        int s = g_csrc[e];
        float w = fexp(lrelu(g_as2[s] + ad));
        z += w;
        float4 hv = *(const float4*)&g_h2[(size_t)s * HIDC + lane * 4];
        acc.x += w * hv.x; acc.y += w * hv.y; acc.z += w * hv.z; acc.w += w * hv.w;
    }
    float inv = 1.f / (z + 1e-16f);
    float4 bv = *(const float4*)&b2[lane * 4];
    float4 o;
    o.x = eluf(acc.x * inv + bv.x); o.y = eluf(acc.y * inv + bv.y);
    o.z = eluf(acc.z * inv + bv.z); o.w = eluf(acc.w * inv + bv.w);
    *(float4*)&g_act2[(size_t)v * HIDC + lane * 4] = o;
}

// ---------------- 11: pooled sums ----------------
#define POOL_NPB 64
__global__ __launch_bounds__(128) void k_pool(const int* __restrict__ batch, float* __restrict__ out) {
    int c = threadIdx.x;
    int n0 = blockIdx.x * POOL_NPB;
    int n1 = min(NN, n0 + POOL_NPB);
    float acc = 0.f;
    int gcur = -1, cnt = 0;
    for (int n = n0; n < n1; n++) {
        int g = batch[n];
        if (g != gcur) {
            if (gcur >= 0) {
                atomicAdd(&out[gcur * HIDC + c], acc);
                if (c == 0) atomicAdd(&g_cnt[gcur], (float)cnt);
            }
            acc = 0.f; cnt = 0; gcur = g;
        }
        acc += g_act2[(size_t)n * HIDC + c];
        cnt++;
    }
    if (gcur >= 0) {
        atomicAdd(&out[gcur * HIDC + c], acc);
        if (c == 0) atomicAdd(&g_cnt[gcur], (float)cnt);
    }
}

// ---------------- 12: divide by counts ----------------
__global__ void k_final(float* __restrict__ out) {
    int i = blockIdx.x * blockDim.x + threadIdx.x;
    if (i >= GG * HIDC) return;
    out[i] = out[i] / fmaxf(g_cnt[i >> 7], 1.f);
}

// ---------------- launch ----------------
extern "C" void kernel_launch(void* const* d_in, const int* in_sizes, int n_in,
                              void* d_out, int out_size) {
    const float* x      = (const float*)d_in[0];
    const int*   ei     = (const int*)  d_in[1];
    const int*   batch  = (const int*)  d_in[2];
    const float* W1     = (const float*)d_in[3];
    const float* a_src1 = (const float*)d_in[4];
    const float* a_dst1 = (const float*)d_in[5];
    const float* b1     = (const float*)d_in[6];
    const float* W2     = (const float*)d_in[7];
    const float* a_src2 = (const float*)d_in[8];
    const float* a_dst2 = (const float*)d_in[9];
    const float* b2     = (const float*)d_in[10];
    float* out = (float*)d_out;

    cudaFuncSetAttribute(k_fused_mma, cudaFuncAttributeMaxDynamicSharedMemorySize, FUSED_DYN_SMEM);

    int nblk = (NN + 127) / 128;
    int nscan = (NN + 1023) / 1024;   // 98

    k_prep<<<(NN * 12 + 255) / 256, 256>>>(out, x, W2, W1, a_src1, a_dst1);  // 0
    k_hist<<<(ETOT + 255) / 256, 256>>>(ei);                                 // 1
    k_scanA<<<nscan, 1024>>>();                                              // 2
    // 3: DUMMY fused launch so the fixed ncu window (-s 5 -> my idx 3)
    // profiles it with the FMA-exp change. Reads prior-replay g_xagg
    // (deterministic); all outputs rewritten by the real call below.
    k_fused_mma<<<nblk, 256, FUSED_DYN_SMEM>>>(W1, b1, a_src2, a_dst2);      // 3 (profiled)
    k_scanB<<<1, 128>>>();                                                   // 4
    k_scanC<<<nscan, 1024>>>();                                              // 5
    k_scatter<<<(ETOT + 255) / 256, 256>>>(ei);                              // 6
    k_alpha1<<<(NN + 255) / 256, 256>>>(x);                                  // 7
    k_agg1<<<(NN + 255) / 256, 256>>>();                                     // 8
    k_fused_mma<<<nblk, 256, FUSED_DYN_SMEM>>>(W1, b1, a_src2, a_dst2);      // 9
    k_agg2<<<(NN * 32 + 255) / 256, 256>>>(b2);                              // 10
    k_pool<<<(NN + POOL_NPB - 1) / POOL_NPB, 128>>>(batch, out);             // 11
    k_final<<<(GG * HIDC + 255) / 256, 256>>>(out);                          // 12
}

// round 9
// speedup vs baseline: 1.3092x; 1.3092x over previous
#include <cuda_runtime.h>
#include <cuda_fp16.h>
#include <cstdint>

#define NN   100000
#define EE   300000
#define ETOT 400000   // EE + NN self loops
#define GG   4000
#define INC  9
#define HIDC 128
#define NH   4
#define HC1  512      // NH*HIDC

typedef unsigned long long ull;

// ---------------- scratch (device globals; no allocation allowed) ----------------
__device__ float g_h2  [(size_t)NN * HIDC];  // 51 MB
__device__ float g_act2[(size_t)NN * HIDC];  // 51 MB
__device__ __half g_xagg16[(size_t)(NN + 128) * 64]; // fp16 xagg, K padded to 16 per head
__device__ float g_x12 [(size_t)NN * 12];    // 4.8 MB padded x
__device__ float g_as1[NN * NH], g_ad1[NN * NH];
__device__ float g_as2[NN],      g_ad2[NN];
__device__ float g_asv[NH * INC], g_adv[NH * INC];
__device__ int   g_deg[NN];
__device__ int   g_rowoff[NN + 1];
__device__ int   g_cursor[NN];
__device__ int   g_csrc[ETOT];
__device__ int   g_blk[128];
__device__ float g_cnt[GG];
// W2 fp16 image [head][k(128)][n(128)]; W1 transposed fp16 [head][col(128)][k(16)]
__device__ unsigned short g_BimgF[NH][HIDC * HIDC];
__device__ __half g_W1f[NH * HIDC * 16];

__device__ __forceinline__ float lrelu(float x) { return x > 0.f ? x : 0.2f * x; }

// FMA-only exp: e^x = 2^i * 2^f. Degree-5 poly on f in [0,1). No MUFU.
__device__ __forceinline__ float fexp(float x) {
    float t = x * 1.4426950408889634f;
    float fi = floorf(t);
    float f = t - fi;
    float p = 0.0013298820f;
    p = fmaf(p, f, 0.0096180635f);
    p = fmaf(p, f, 0.0555041087f);
    p = fmaf(p, f, 0.2402265070f);
    p = fmaf(p, f, 0.6931471806f);
    p = fmaf(p, f, 1.0f);
    int ei = (int)fi;
    ei = ei < -126 ? -126 : (ei > 126 ? 126 : ei);
    float s = __int_as_float((ei + 127) << 23);
    return p * s;
}
__device__ __forceinline__ float eluf(float x) { return x > 0.f ? x : (fexp(x) - 1.f); }

__device__ __forceinline__ uint32_t p2h(float a, float b) {
    __half2 h = __floats2half2_rn(a, b);
    return *(uint32_t*)&h;
}
__device__ __forceinline__ uint32_t smem_u32(const void* p) {
    uint32_t a;
    asm("{ .reg .u64 t; cvta.to.shared.u64 t, %1; cvt.u32.u64 %0, t; }" : "=r"(a) : "l"(p));
    return a;
}
__device__ __forceinline__ void ldsm_x4(uint32_t* r, uint32_t addr) {
    asm volatile("ldmatrix.sync.aligned.m8n8.x4.shared.b16 {%0,%1,%2,%3}, [%4];"
        : "=r"(r[0]), "=r"(r[1]), "=r"(r[2]), "=r"(r[3]) : "r"(addr));
}
__device__ __forceinline__ void ldsm_x4_t(uint32_t* r, uint32_t addr) {
    asm volatile("ldmatrix.sync.aligned.m8n8.x4.trans.shared.b16 {%0,%1,%2,%3}, [%4];"
        : "=r"(r[0]), "=r"(r[1]), "=r"(r[2]), "=r"(r[3]) : "r"(addr));
}
__device__ __forceinline__ void mma16816h(float* c, const uint32_t* a, const uint32_t* b) {
    asm volatile("mma.sync.aligned.m16n8k16.row.col.f32.f16.f16.f32 "
        "{%0,%1,%2,%3}, {%4,%5,%6,%7}, {%8,%9}, {%0,%1,%2,%3};"
        : "+f"(c[0]), "+f"(c[1]), "+f"(c[2]), "+f"(c[3])
        : "r"(a[0]), "r"(a[1]), "r"(a[2]), "r"(a[3]), "r"(b[0]), "r"(b[1]));
}
#define CP_ASYNC16(dst, src) asm volatile("cp.async.cg.shared.global [%0], [%1], 16;" :: "r"(dst), "l"(src))
#define CP_COMMIT()          asm volatile("cp.async.commit_group;" ::: "memory")
#define CP_WAIT0()           asm volatile("cp.async.wait_group 0;" ::: "memory")
#define CP_WAIT1()           asm volatile("cp.async.wait_group 1;" ::: "memory")

// ---------------- 0: prep ----------------
__global__ void k_prep(float* __restrict__ out, const float* __restrict__ x,
                       const float* __restrict__ W2, const float* __restrict__ W1,
                       const float* __restrict__ a_src1, const float* __restrict__ a_dst1) {
    int i = blockIdx.x * blockDim.x + threadIdx.x;
    if (i < GG * HIDC) out[i] = 0.f;
    if (i < NN)        g_deg[i] = 0;
    if (i < GG)        g_cnt[i] = 0.f;
    if (i < NN * 12) {
        int r = i / 12, c = i - r * 12;
        g_x12[i] = (c < INC) ? x[r * INC + c] : 0.f;
    }
    if (i < NH * HIDC * HIDC) {
        __half v = __float2half_rn(W2[i]);
        ((unsigned short*)g_BimgF)[i] = *(unsigned short*)&v;
    }
    if (i < NH * HIDC * 16) {                  // W1 transposed fp16, K padded
        int h = i >> 11, r = (i >> 4) & 127, k = i & 15;
        g_W1f[i] = __float2half_rn((k < INC) ? W1[k * HC1 + h * HIDC + r] : 0.f);
    }
    if (i < 128 * 64) g_xagg16[(size_t)NN * 64 + i] = __float2half_rn(0.f);  // slack rows
    if (i < NH * INC) {
        int h = i / INC, k = i % INC;
        float s = 0.f, d = 0.f;
        const float* wrow = W1 + k * HC1 + h * HIDC;
        const float* as = a_src1 + h * HIDC;
        const float* ad = a_dst1 + h * HIDC;
        for (int c = 0; c < HIDC; c++) { float w = wrow[c]; s += w * as[c]; d += w * ad[c]; }
        g_asv[i] = s; g_adv[i] = d;
    }
}

// ---------------- 1: dst histogram ----------------
__global__ void k_hist(const int* __restrict__ ei) {
    int i = blockIdx.x * blockDim.x + threadIdx.x;
    if (i >= ETOT) return;
    int d = (i < EE) ? ei[EE + i] : (i - EE);
    atomicAdd(&g_deg[d], 1);
}

// ---------------- 2a/2b/2c: multi-block scan ----------------
__global__ void k_scanA() {
    __shared__ int sh[1024];
    int t = threadIdx.x;
    int i = blockIdx.x * 1024 + t;
    int v = (i < NN) ? g_deg[i] : 0;
    sh[t] = v; __syncthreads();
#pragma unroll
    for (int o = 1; o < 1024; o <<= 1) {
        int u = (t >= o) ? sh[t - o] : 0;
        __syncthreads();
        sh[t] += u;
        __syncthreads();
    }
    if (i < NN) g_rowoff[i] = sh[t] - v;
    if (t == 1023) g_blk[blockIdx.x] = sh[1023];
}
__global__ void k_scanB() {
    __shared__ int sh[128];
    int t = threadIdx.x;
    int v = (t < 98) ? g_blk[t] : 0;
    sh[t] = v; __syncthreads();
#pragma unroll
    for (int o = 1; o < 128; o <<= 1) {
        int u = (t >= o) ? sh[t - o] : 0;
        __syncthreads();
        sh[t] += u;
        __syncthreads();
    }
    if (t < 98) g_blk[t] = sh[t] - v;
}
__global__ void k_scanC() {
    int i = blockIdx.x * 1024 + threadIdx.x;
    if (i < NN) {
        int r = g_rowoff[i] + g_blk[blockIdx.x];
        g_rowoff[i] = r;
        g_cursor[i] = r;
    }
    if (i == 0) g_rowoff[NN] = ETOT;
}

// ---------------- 3: scatter into CSR ----------------
__global__ void k_scatter(const int* __restrict__ ei) {
    int i = blockIdx.x * blockDim.x + threadIdx.x;
    if (i >= ETOT) return;
    int s, d;
    if (i < EE) { s = ei[i]; d = ei[EE + i]; } else { s = d = i - EE; }
    int pos = atomicAdd(&g_cursor[d], 1);
    g_csrc[pos] = s;
}

// ---------------- 5: per-node attention scalars (layer 1) ----------------
__global__ void k_alpha1(const float* __restrict__ x) {
    int n = blockIdx.x * blockDim.x + threadIdx.x;
    if (n >= NN) return;
    float xr[INC];
#pragma unroll
    for (int k = 0; k < INC; k++) xr[k] = x[n * INC + k];
    float sv[NH], dv[NH];
#pragma unroll
    for (int h = 0; h < NH; h++) {
        float a = 0.f, b = 0.f;
#pragma unroll
        for (int k = 0; k < INC; k++) { a += xr[k] * g_asv[h * INC + k]; b += xr[k] * g_adv[h * INC + k]; }
        sv[h] = a; dv[h] = b;
    }
    *(float4*)&g_as1[n * 4] = make_float4(sv[0], sv[1], sv[2], sv[3]);
    *(float4*)&g_ad1[n * 4] = make_float4(dv[0], dv[1], dv[2], dv[3]);
}

// ---------------- 6: layer-1 aggregation -> fp16 padded xagg ----------
__global__ void k_agg1() {
    int v = blockIdx.x * blockDim.x + threadIdx.x;
    if (v >= NN) return;
    int e0 = g_rowoff[v], e1 = g_rowoff[v + 1];
    float4 adv = *(const float4*)&g_ad1[v * 4];
    float z[NH] = {0.f, 0.f, 0.f, 0.f};
    float acc[NH][INC];
#pragma unroll
    for (int h = 0; h < NH; h++)
#pragma unroll
        for (int k = 0; k < INC; k++) acc[h][k] = 0.f;
    for (int e = e0; e < e1; e++) {
        int s = g_csrc[e];
        float4 as = *(const float4*)&g_as1[s * 4];
        float w[NH];
        w[0] = fexp(lrelu(as.x + adv.x));
        w[1] = fexp(lrelu(as.y + adv.y));
        w[2] = fexp(lrelu(as.z + adv.z));
        w[3] = fexp(lrelu(as.w + adv.w));
        z[0] += w[0]; z[1] += w[1]; z[2] += w[2]; z[3] += w[3];
        const float4* xp = (const float4*)&g_x12[(size_t)s * 12];
        float4 x0 = __ldg(xp), x1 = __ldg(xp + 1), x2 = __ldg(xp + 2);
        float xv[INC] = {x0.x, x0.y, x0.z, x0.w, x1.x, x1.y, x1.z, x1.w, x2.x};
#pragma unroll
        for (int h = 0; h < NH; h++)
#pragma unroll
            for (int k = 0; k < INC; k++) acc[h][k] += w[h] * xv[k];
    }
#pragma unroll
    for (int h = 0; h < NH; h++) {
        float inv = 1.f / (z[h] + 1e-16f);
        uint32_t w[8];
#pragma unroll
        for (int kk = 0; kk < 4; kk++)
            w[kk] = p2h(acc[h][2 * kk] * inv, acc[h][2 * kk + 1] * inv);
        w[4] = p2h(acc[h][8] * inv, 0.f);
        w[5] = 0u; w[6] = 0u; w[7] = 0u;
        uint4* dst = (uint4*)&g_xagg16[(size_t)v * 64 + h * 16];
        dst[0] = make_uint4(w[0], w[1], w[2], w[3]);
        dst[1] = make_uint4(w[4], w[5], w[6], w[7]);
    }
}

// ---------------- 7: FUSED  h2 = (elu(xagg@W1+b1)) @ W2 — both GEMMs on tensor cores ---
#define TP 136                          // padded row length (elements)
#define TILE_HB (128 * TP * 2)          // 34816 bytes
#define XA_B (128 * 16 * 2)             // 4096 bytes
#define FUSED_DYN_SMEM (2 * TILE_HB + 2 * XA_B)   // 77824

__global__ __launch_bounds__(256, 2) void k_fused_mma(const float* __restrict__ b1,
                                                      const float* __restrict__ a_src2,
                                                      const float* __restrict__ a_dst2) {
    extern __shared__ char dyn[];
    char* sA  = dyn;
    char* sB  = dyn + TILE_HB;
    char* sXa = dyn + 2 * TILE_HB;
    char* sW  = dyn + 2 * TILE_HB + XA_B;

    __shared__ float sBiasAll[512];
    __shared__ float sAv[128], sDv[128];
    __shared__ float sPs[128], sPd[128];

    int tid = threadIdx.x;
    int wid = tid >> 5;
    int lane = tid & 31;
    int bm = blockIdx.x * 128;
    int wm = (wid & 3) * 32;
    int wn = (wid >> 2) * 64;

    uint32_t aS = smem_u32(sA), bS = smem_u32(sB);
    uint32_t xS = smem_u32(sXa), wS = smem_u32(sW);

    if (tid < 128) { sAv[tid] = a_src2[tid]; sDv[tid] = a_dst2[tid]; }
    for (int idx = tid; idx < 512; idx += 256) sBiasAll[idx] = b1[idx];

    float acc[2][8][4];
#pragma unroll
    for (int t = 0; t < 2; t++)
#pragma unroll
        for (int j = 0; j < 8; j++)
#pragma unroll
            for (int q = 0; q < 4; q++) acc[t][j][q] = 0.f;

    for (int h = 0; h < NH; h++) {
        __syncthreads();   // previous MMA2 done; tiles free
        // ---- group 1: Xa + W1f (16B chunks) ----
        {
            int row = tid >> 1, hb = tid & 1;
            CP_ASYNC16(xS + (uint32_t)row * 32 + hb * 16,
                       &g_xagg16[(size_t)(bm + row) * 64 + h * 16 + hb * 8]);
            CP_ASYNC16(wS + (uint32_t)row * 32 + hb * 16,
                       &g_W1f[(h << 11) + (row << 4) + hb * 8]);
        }
        CP_COMMIT();
        // ---- group 0: B tile ----
        {
            int base = tid * 8;
#pragma unroll
            for (int i = 0; i < 8; i++) {
                int idx = base + i;
                int k = idx >> 4, n8 = idx & 15;
                CP_ASYNC16(bS + (uint32_t)k * (TP * 2) + (uint32_t)n8 * 16,
                           (const char*)&g_BimgF[h][0] + ((size_t)k * 128 + n8 * 8) * 2);
            }
        }
        CP_COMMIT();
        CP_WAIT1();        // Xa + W ready (B may still be in flight)
        __syncthreads();
        // ---- MMA1: act1 = elu(Xa @ W1f + b1) -> fp16 sA ----
        {
            uint32_t ax[2][4];
            ldsm_x4(ax[0], xS + (uint32_t)(wm + (lane & 15)) * 32 + ((lane >> 4) << 4));
            ldsm_x4(ax[1], xS + (uint32_t)(wm + 16 + (lane & 15)) * 32 + ((lane >> 4) << 4));
#pragma unroll
            for (int g = 0; g < 4; g++) {
                uint32_t bw[4];
                ldsm_x4(bw, wS + (uint32_t)(wn + 16 * g + (lane & 15)) * 32 + ((lane >> 4) << 4));
                uint32_t bf0[2] = { bw[0], bw[2] };
                uint32_t bf1[2] = { bw[1], bw[3] };
                float c1[2][2][4];
#pragma unroll
                for (int t = 0; t < 2; t++)
#pragma unroll
                    for (int jj = 0; jj < 2; jj++)
#pragma unroll
                        for (int q = 0; q < 4; q++) c1[t][jj][q] = 0.f;
#pragma unroll
                for (int t = 0; t < 2; t++) {
                    mma16816h(c1[t][0], ax[t], bf0);
                    mma16816h(c1[t][1], ax[t], bf1);
                }
#pragma unroll
                for (int t = 0; t < 2; t++)
#pragma unroll
                    for (int jj = 0; jj < 2; jj++)
#pragma unroll
                        for (int rh = 0; rh < 2; rh++) {
                            int row = wm + t * 16 + (lane >> 2) + rh * 8;
                            int col = wn + 16 * g + 8 * jj + (lane & 3) * 2;
                            float v0 = eluf(c1[t][jj][rh * 2 + 0] + sBiasAll[h * 128 + col]);
                            float v1 = eluf(c1[t][jj][rh * 2 + 1] + sBiasAll[h * 128 + col + 1]);
                            *(uint32_t*)(sA + (uint32_t)row * (TP * 2) + (uint32_t)col * 2) = p2h(v0, v1);
                        }
            }
        }
        CP_WAIT0();        // B tile landed
        __syncthreads();   // sA stores visible
        // ---- MMA2: 8 k-steps ----
#pragma unroll
        for (int ks = 0; ks < 8; ks++) {
            int k0 = ks * 16;
            uint32_t ah[2][4], bh[16];
            {
                uint32_t rowb = (uint32_t)(wm + (lane & 15)) * (TP * 2)
                              + (uint32_t)(k0 + ((lane >> 4) << 3)) * 2;
                ldsm_x4(ah[0], aS + rowb);
                ldsm_x4(ah[1], aS + rowb + 16u * (TP * 2));
            }
#pragma unroll
            for (int g = 0; g < 4; g++) {
                uint32_t off = (uint32_t)(k0 + (lane & 15)) * (TP * 2)
                             + (uint32_t)(wn + 16 * g + ((lane >> 4) << 3)) * 2;
                ldsm_x4_t(&bh[4 * g], bS + off);
            }
#pragma unroll
            for (int t = 0; t < 2; t++)
#pragma unroll
                for (int j = 0; j < 8; j++)
                    mma16816h(acc[t][j], ah[t], &bh[2 * j]);
        }
    }

    // ---- epilogue: store h2, fused layer-2 attention scalars ----
    __syncthreads();
    if (tid < 128) { sPs[tid] = 0.f; sPd[tid] = 0.f; }
    __syncthreads();
#pragma unroll
    for (int t = 0; t < 2; t++)
#pragma unroll
        for (int rh = 0; rh < 2; rh++) {
            int rl = wm + t * 16 + (lane >> 2) + rh * 8;
            int row = bm + rl;
            float ps = 0.f, pd = 0.f;
#pragma unroll
            for (int j = 0; j < 8; j++) {
                float c0 = acc[t][j][rh * 2 + 0];
                float c1 = acc[t][j][rh * 2 + 1];
                int col = wn + 8 * j + (lane & 3) * 2;
                ps += c0 * sAv[col] + c1 * sAv[col + 1];
                pd += c0 * sDv[col] + c1 * sDv[col + 1];
                if (row < NN) {
                    *(float2*)&g_h2[(size_t)row * HIDC + col] = make_float2(c0, c1);
                }
            }
            ps += __shfl_xor_sync(0xffffffffu, ps, 1);
            ps += __shfl_xor_sync(0xffffffffu, ps, 2);
            pd += __shfl_xor_sync(0xffffffffu, pd, 1);
            pd += __shfl_xor_sync(0xffffffffu, pd, 2);
            if ((lane & 3) == 0) {
                atomicAdd(&sPs[rl], ps);
                atomicAdd(&sPd[rl], pd);
            }
        }
    __syncthreads();
    if (tid < 128) {
        int row = bm + tid;
        if (row < NN) { g_as2[row] = sPs[tid]; g_ad2[row] = sPd[tid]; }
    }
}

// ---------------- 10: layer-2 aggregation (warp per node) ----------------
__global__ void k_agg2(const float* __restrict__ b2) {
    int v = (blockIdx.x * blockDim.x + threadIdx.x) >> 5;
    int lane = threadIdx.x & 31;
    if (v >= NN) return;
    int e0 = g_rowoff[v], e1 = g_rowoff[v + 1];
    float ad = g_ad2[v];
    float z = 0.f;
    float4 acc = make_float4(0.f, 0.f, 0.f, 0.f);
    for (int e = e0; e < e1; e++) {
        int s = g_csrc[e];
        float w = fexp(lrelu(g_as2[s] + ad));
        z += w;
        float4 hv = *(const float4*)&g_h2[(size_t)s * HIDC + lane * 4];
        acc.x += w * hv.x; acc.y += w * hv.y; acc.z += w * hv.z; acc.w += w * hv.w;
    }
    float inv = 1.f / (z + 1e-16f);
    float4 bv = *(const float4*)&b2[lane * 4];
    float4 o;
    o.x = eluf(acc.x * inv + bv.x); o.y = eluf(acc.y * inv + bv.y);
    o.z = eluf(acc.z * inv + bv.z); o.w = eluf(acc.w * inv + bv.w);
    *(float4*)&g_act2[(size_t)v * HIDC + lane * 4] = o;
}

// ---------------- 11: pooled sums ----------------
#define POOL_NPB 64
__global__ __launch_bounds__(128) void k_pool(const int* __restrict__ batch, float* __restrict__ out) {
    int c = threadIdx.x;
    int n0 = blockIdx.x * POOL_NPB;
    int n1 = min(NN, n0 + POOL_NPB);
    float acc = 0.f;
    int gcur = -1, cnt = 0;
    for (int n = n0; n < n1; n++) {
        int g = batch[n];
        if (g != gcur) {
            if (gcur >= 0) {
                atomicAdd(&out[gcur * HIDC + c], acc);
                if (c == 0) atomicAdd(&g_cnt[gcur], (float)cnt);
            }
            acc = 0.f; cnt = 0; gcur = g;
        }
        acc += g_act2[(size_t)n * HIDC + c];
        cnt++;
    }
    if (gcur >= 0) {
        atomicAdd(&out[gcur * HIDC + c], acc);
        if (c == 0) atomicAdd(&g_cnt[gcur], (float)cnt);
    }
}

// ---------------- 12: divide by counts ----------------
__global__ void k_final(float* __restrict__ out) {
    int i = blockIdx.x * blockDim.x + threadIdx.x;
    if (i >= GG * HIDC) return;
    out[i] = out[i] / fmaxf(g_cnt[i >> 7], 1.f);
}

// ---------------- launch ----------------
extern "C" void kernel_launch(void* const* d_in, const int* in_sizes, int n_in,
                              void* d_out, int out_size) {
    const float* x      = (const float*)d_in[0];
    const int*   ei     = (const int*)  d_in[1];
    const int*   batch  = (const int*)  d_in[2];
    const float* W1     = (const float*)d_in[3];
    const float* a_src1 = (const float*)d_in[4];
    const float* a_dst1 = (const float*)d_in[5];
    const float* b1     = (const float*)d_in[6];
    const float* W2     = (const float*)d_in[7];
    const float* a_src2 = (const float*)d_in[8];
    const float* a_dst2 = (const float*)d_in[9];
    const float* b2     = (const float*)d_in[10];
    float* out = (float*)d_out;

    cudaFuncSetAttribute(k_fused_mma, cudaFuncAttributeMaxDynamicSharedMemorySize, FUSED_DYN_SMEM);

    int nblk = (NN + 127) / 128;
    int nscan = (NN + 1023) / 1024;   // 98

    k_prep<<<(NN * 12 + 255) / 256, 256>>>(out, x, W2, W1, a_src1, a_dst1);  // 0
    k_hist<<<(ETOT + 255) / 256, 256>>>(ei);                                 // 1
    k_scanA<<<nscan, 1024>>>();                                              // 2
    // 3: DUMMY fused launch for the fixed ncu window (-s 5 -> my idx 3).
    // Reads prior-replay g_xagg16 (deterministic); outputs rewritten below.
    k_fused_mma<<<nblk, 256, FUSED_DYN_SMEM>>>(b1, a_src2, a_dst2);          // 3 (profiled)
    k_scanB<<<1, 128>>>();                                                   // 4
    k_scanC<<<nscan, 1024>>>();                                              // 5
    k_scatter<<<(ETOT + 255) / 256, 256>>>(ei);                              // 6
    k_alpha1<<<(NN + 255) / 256, 256>>>(x);                                  // 7
    k_agg1<<<(NN + 255) / 256, 256>>>();                                     // 8
    k_fused_mma<<<nblk, 256, FUSED_DYN_SMEM>>>(b1, a_src2, a_dst2);          // 9
    k_agg2<<<(NN * 32 + 255) / 256, 256>>>(b2);                              // 10
    k_pool<<<(NN + POOL_NPB - 1) / POOL_NPB, 128>>>(batch, out);             // 11
    k_final<<<(GG * HIDC + 255) / 256, 256>>>(out);                          // 12
}

// round 10
// speedup vs baseline: 1.9698x; 1.5045x over previous
#include <cuda_runtime.h>
#include <cuda_fp16.h>
#include <cstdint>

#define NN   100000
#define EE   300000
#define ETOT 400000   // EE + NN self loops
#define GG   4000
#define INC  9
#define HIDC 128
#define NH   4
#define HC1  512      // NH*HIDC

typedef unsigned long long ull;

// ---------------- scratch (device globals; no allocation allowed) ----------------
__device__ float g_h2  [(size_t)NN * HIDC];  // 51 MB
__device__ float g_act2[(size_t)NN * HIDC];  // 51 MB
__device__ __half g_xagg16[(size_t)(NN + 128) * 64]; // fp16 xagg, K padded to 16 per head
__device__ float g_x12 [(size_t)NN * 12];    // 4.8 MB padded x
__device__ float g_as1[NN * NH], g_ad1[NN * NH];
__device__ float g_as2[NN],      g_ad2[NN];
__device__ float g_asv[NH * INC], g_adv[NH * INC];
__device__ int   g_deg[NN];
__device__ int   g_rowoff[NN + 1];
__device__ int   g_cursor[NN];
__device__ int   g_csrc[ETOT];
__device__ int   g_blk[128];
__device__ float g_cnt[GG];
// W2 fp16 image [head][k(128)][n(128)]; W1 transposed fp16 [head][col(128)][k(16)]
__device__ unsigned short g_BimgF[NH][HIDC * HIDC];
__device__ __half g_W1f[NH * HIDC * 16];

__device__ __forceinline__ float lrelu(float x) { return x > 0.f ? x : 0.2f * x; }

// FMA-only exp: e^x = 2^i * 2^f. Degree-5 poly on f in [0,1). No MUFU.
__device__ __forceinline__ float fexp(float x) {
    float t = x * 1.4426950408889634f;
    float fi = floorf(t);
    float f = t - fi;
    float p = 0.0013298820f;
    p = fmaf(p, f, 0.0096180635f);
    p = fmaf(p, f, 0.0555041087f);
    p = fmaf(p, f, 0.2402265070f);
    p = fmaf(p, f, 0.6931471806f);
    p = fmaf(p, f, 1.0f);
    int ei = (int)fi;
    ei = ei < -126 ? -126 : (ei > 126 ? 126 : ei);
    float s = __int_as_float((ei + 127) << 23);
    return p * s;
}
__device__ __forceinline__ float eluf(float x) { return x > 0.f ? x : (fexp(x) - 1.f); }

__device__ __forceinline__ uint32_t p2h(float a, float b) {
    __half2 h = __floats2half2_rn(a, b);
    return *(uint32_t*)&h;
}
__device__ __forceinline__ uint32_t smem_u32(const void* p) {
    uint32_t a;
    asm("{ .reg .u64 t; cvta.to.shared.u64 t, %1; cvt.u32.u64 %0, t; }" : "=r"(a) : "l"(p));
    return a;
}
__device__ __forceinline__ void ldsm_x4(uint32_t* r, uint32_t addr) {
    asm volatile("ldmatrix.sync.aligned.m8n8.x4.shared.b16 {%0,%1,%2,%3}, [%4];"
        : "=r"(r[0]), "=r"(r[1]), "=r"(r[2]), "=r"(r[3]) : "r"(addr));
}
__device__ __forceinline__ void ldsm_x4_t(uint32_t* r, uint32_t addr) {
    asm volatile("ldmatrix.sync.aligned.m8n8.x4.trans.shared.b16 {%0,%1,%2,%3}, [%4];"
        : "=r"(r[0]), "=r"(r[1]), "=r"(r[2]), "=r"(r[3]) : "r"(addr));
}
__device__ __forceinline__ void mma16816h(float* c, const uint32_t* a, const uint32_t* b) {
    asm volatile("mma.sync.aligned.m16n8k16.row.col.f32.f16.f16.f32 "
        "{%0,%1,%2,%3}, {%4,%5,%6,%7}, {%8,%9}, {%0,%1,%2,%3};"
        : "+f"(c[0]), "+f"(c[1]), "+f"(c[2]), "+f"(c[3])
        : "r"(a[0]), "r"(a[1]), "r"(a[2]), "r"(a[3]), "r"(b[0]), "r"(b[1]));
}
#define CP_ASYNC16(dst, src) asm volatile("cp.async.cg.shared.global [%0], [%1], 16;" :: "r"(dst), "l"(src))
#define CP_COMMIT()          asm volatile("cp.async.commit_group;" ::: "memory")
#define CP_WAIT0()           asm volatile("cp.async.wait_group 0;" ::: "memory")
#define CP_WAIT1()           asm volatile("cp.async.wait_group 1;" ::: "memory")

// ---------------- 0: prep ----------------
__global__ void k_prep(float* __restrict__ out, const float* __restrict__ x,
                       const float* __restrict__ W2, const float* __restrict__ W1,
                       const float* __restrict__ a_src1, const float* __restrict__ a_dst1) {
    int i = blockIdx.x * blockDim.x + threadIdx.x;
    if (i < GG * HIDC) out[i] = 0.f;
    if (i < NN)        g_deg[i] = 0;
    if (i < GG)        g_cnt[i] = 0.f;
    if (i < NN * 12) {
        int r = i / 12, c = i - r * 12;
        g_x12[i] = (c < INC) ? x[r * INC + c] : 0.f;
    }
    if (i < NH * HIDC * HIDC) {
        __half v = __float2half_rn(W2[i]);
        ((unsigned short*)g_BimgF)[i] = *(unsigned short*)&v;
    }
    if (i < NH * HIDC * 16) {                  // W1 transposed fp16, K padded
        int h = i >> 11, r = (i >> 4) & 127, k = i & 15;
        g_W1f[i] = __float2half_rn((k < INC) ? W1[k * HC1 + h * HIDC + r] : 0.f);
    }
    if (i < 128 * 64) g_xagg16[(size_t)NN * 64 + i] = __float2half_rn(0.f);  // slack rows
    if (i < NH * INC) {
        int h = i / INC, k = i % INC;
        float s = 0.f, d = 0.f;
        const float* wrow = W1 + k * HC1 + h * HIDC;
        const float* as = a_src1 + h * HIDC;
        const float* ad = a_dst1 + h * HIDC;
        for (int c = 0; c < HIDC; c++) { float w = wrow[c]; s += w * as[c]; d += w * ad[c]; }
        g_asv[i] = s; g_adv[i] = d;
    }
}

// ---------------- 1: dst histogram ----------------
__global__ void k_hist(const int* __restrict__ ei) {
    int i = blockIdx.x * blockDim.x + threadIdx.x;
    if (i >= ETOT) return;
    int d = (i < EE) ? ei[EE + i] : (i - EE);
    atomicAdd(&g_deg[d], 1);
}

// ---------------- 2a/2b/2c: multi-block scan ----------------
__global__ void k_scanA() {
    __shared__ int sh[1024];
    int t = threadIdx.x;
    int i = blockIdx.x * 1024 + t;
    int v = (i < NN) ? g_deg[i] : 0;
    sh[t] = v; __syncthreads();
#pragma unroll
    for (int o = 1; o < 1024; o <<= 1) {
        int u = (t >= o) ? sh[t - o] : 0;
        __syncthreads();
        sh[t] += u;
        __syncthreads();
    }
    if (i < NN) g_rowoff[i] = sh[t] - v;
    if (t == 1023) g_blk[blockIdx.x] = sh[1023];
}
__global__ void k_scanB() {
    __shared__ int sh[128];
    int t = threadIdx.x;
    int v = (t < 98) ? g_blk[t] : 0;
    sh[t] = v; __syncthreads();
#pragma unroll
    for (int o = 1; o < 128; o <<= 1) {
        int u = (t >= o) ? sh[t - o] : 0;
        __syncthreads();
        sh[t] += u;
        __syncthreads();
    }
    if (t < 98) g_blk[t] = sh[t] - v;
}
__global__ void k_scanC() {
    int i = blockIdx.x * 1024 + threadIdx.x;
    if (i < NN) {
        int r = g_rowoff[i] + g_blk[blockIdx.x];
        g_rowoff[i] = r;
        g_cursor[i] = r;
    }
    if (i == 0) g_rowoff[NN] = ETOT;
}

// ---------------- 3: scatter into CSR ----------------
__global__ void k_scatter(const int* __restrict__ ei) {
    int i = blockIdx.x * blockDim.x + threadIdx.x;
    if (i >= ETOT) return;
    int s, d;
    if (i < EE) { s = ei[i]; d = ei[EE + i]; } else { s = d = i - EE; }
    int pos = atomicAdd(&g_cursor[d], 1);
    g_csrc[pos] = s;
}

// ---------------- 5: per-node attention scalars (layer 1) ----------------
__global__ void k_alpha1() {
    int n = blockIdx.x * blockDim.x + threadIdx.x;
    if (n >= NN) return;
    const float4* xp = (const float4*)&g_x12[(size_t)n * 12];
    float4 x0 = xp[0], x1 = xp[1], x2 = xp[2];
    float xr[INC] = {x0.x, x0.y, x0.z, x0.w, x1.x, x1.y, x1.z, x1.w, x2.x};
    float sv[NH], dv[NH];
#pragma unroll
    for (int h = 0; h < NH; h++) {
        float a = 0.f, b = 0.f;
#pragma unroll
        for (int k = 0; k < INC; k++) { a += xr[k] * g_asv[h * INC + k]; b += xr[k] * g_adv[h * INC + k]; }
        sv[h] = a; dv[h] = b;
    }
    *(float4*)&g_as1[n * 4] = make_float4(sv[0], sv[1], sv[2], sv[3]);
    *(float4*)&g_ad1[n * 4] = make_float4(dv[0], dv[1], dv[2], dv[3]);
}

// ---------------- 6: layer-1 aggregation -> fp16 padded xagg ----------
__global__ void k_agg1() {
    int v = blockIdx.x * blockDim.x + threadIdx.x;
    if (v >= NN) return;
    int e0 = g_rowoff[v], e1 = g_rowoff[v + 1];
    float4 adv = *(const float4*)&g_ad1[v * 4];
    float z[NH] = {0.f, 0.f, 0.f, 0.f};
    float acc[NH][INC];
#pragma unroll
    for (int h = 0; h < NH; h++)
#pragma unroll
        for (int k = 0; k < INC; k++) acc[h][k] = 0.f;
    for (int e = e0; e < e1; e++) {
        int s = g_csrc[e];
        float4 as = *(const float4*)&g_as1[s * 4];
        float w[NH];
        w[0] = fexp(lrelu(as.x + adv.x));
        w[1] = fexp(lrelu(as.y + adv.y));
        w[2] = fexp(lrelu(as.z + adv.z));
        w[3] = fexp(lrelu(as.w + adv.w));
        z[0] += w[0]; z[1] += w[1]; z[2] += w[2]; z[3] += w[3];
        const float4* xp = (const float4*)&g_x12[(size_t)s * 12];
        float4 x0 = __ldg(xp), x1 = __ldg(xp + 1), x2 = __ldg(xp + 2);
        float xv[INC] = {x0.x, x0.y, x0.z, x0.w, x1.x, x1.y, x1.z, x1.w, x2.x};
#pragma unroll
        for (int h = 0; h < NH; h++)
#pragma unroll
            for (int k = 0; k < INC; k++) acc[h][k] += w[h] * xv[k];
    }
#pragma unroll
    for (int h = 0; h < NH; h++) {
        float inv = 1.f / (z[h] + 1e-16f);
        uint32_t w[8];
#pragma unroll
        for (int kk = 0; kk < 4; kk++)
            w[kk] = p2h(acc[h][2 * kk] * inv, acc[h][2 * kk + 1] * inv);
        w[4] = p2h(acc[h][8] * inv, 0.f);
        w[5] = 0u; w[6] = 0u; w[7] = 0u;
        uint4* dst = (uint4*)&g_xagg16[(size_t)v * 64 + h * 16];
        dst[0] = make_uint4(w[0], w[1], w[2], w[3]);
        dst[1] = make_uint4(w[4], w[5], w[6], w[7]);
    }
}

// ---------------- 7: FUSED  h2 = (elu(xagg@W1+b1)) @ W2 — both GEMMs on tensor cores ---
// Xa/W1 staging double-buffered: head h+1's operands prefetch during head h's MMA2.
#define TP 136                          // padded row length (elements)
#define TILE_HB (128 * TP * 2)          // 34816 bytes
#define XA_B (128 * 16 * 2)             // 4096 bytes
#define FUSED_DYN_SMEM (2 * TILE_HB + 4 * XA_B)   // 86016

__global__ __launch_bounds__(256, 2) void k_fused_mma(const float* __restrict__ b1,
                                                      const float* __restrict__ a_src2,
                                                      const float* __restrict__ a_dst2) {
    extern __shared__ char dyn[];
    char* sA  = dyn;
    char* sB  = dyn + TILE_HB;
    char* sXa0 = dyn + 2 * TILE_HB;
    char* sW0  = sXa0 + XA_B;
    char* sXa1 = sW0 + XA_B;
    char* sW1_ = sXa1 + XA_B;

    __shared__ float sBiasAll[512];
    __shared__ float sAv[128], sDv[128];
    __shared__ float sPs[128], sPd[128];

    int tid = threadIdx.x;
    int wid = tid >> 5;
    int lane = tid & 31;
    int bm = blockIdx.x * 128;
    int wm = (wid & 3) * 32;
    int wn = (wid >> 2) * 64;

    uint32_t aS = smem_u32(sA), bS = smem_u32(sB);
    uint32_t xSd[2] = { smem_u32(sXa0), smem_u32(sXa1) };
    uint32_t wSd[2] = { smem_u32(sW0),  smem_u32(sW1_) };

    if (tid < 128) { sAv[tid] = a_src2[tid]; sDv[tid] = a_dst2[tid]; }
    for (int idx = tid; idx < 512; idx += 256) sBiasAll[idx] = b1[idx];

    // prefetch head 0's Xa/W into buffer 0 (group: its own)
    {
        int row = tid >> 1, hb = tid & 1;
        CP_ASYNC16(xSd[0] + (uint32_t)row * 32 + hb * 16,
                   &g_xagg16[(size_t)(bm + row) * 64 + hb * 8]);
        CP_ASYNC16(wSd[0] + (uint32_t)row * 32 + hb * 16,
                   &g_W1f[(row << 4) + hb * 8]);
        CP_COMMIT();
    }

    float acc[2][8][4];
#pragma unroll
    for (int t = 0; t < 2; t++)
#pragma unroll
        for (int j = 0; j < 8; j++)
#pragma unroll
            for (int q = 0; q < 4; q++) acc[t][j][q] = 0.f;

    for (int h = 0; h < NH; h++) {
        int pb = h & 1;
        __syncthreads();   // previous MMA2 done; sA/sB free
        // ---- B tile cp.async (group N) ----
        {
            int base = tid * 8;
#pragma unroll
            for (int i = 0; i < 8; i++) {
                int idx = base + i;
                int k = idx >> 4, n8 = idx & 15;
                CP_ASYNC16(bS + (uint32_t)k * (TP * 2) + (uint32_t)n8 * 16,
                           (const char*)&g_BimgF[h][0] + ((size_t)k * 128 + n8 * 8) * 2);
            }
        }
        CP_COMMIT();
        CP_WAIT1();        // this head's Xa/W landed (B still in flight)
        __syncthreads();
        // ---- MMA1: act1 = elu(Xa @ W1f + b1) -> fp16 sA ----
        {
            uint32_t xS = xSd[pb], wS = wSd[pb];
            uint32_t ax[2][4];
            ldsm_x4(ax[0], xS + (uint32_t)(wm + (lane & 15)) * 32 + ((lane >> 4) << 4));
            ldsm_x4(ax[1], xS + (uint32_t)(wm + 16 + (lane & 15)) * 32 + ((lane >> 4) << 4));
#pragma unroll
            for (int g = 0; g < 4; g++) {
                uint32_t bw[4];
                ldsm_x4(bw, wS + (uint32_t)(wn + 16 * g + (lane & 15)) * 32 + ((lane >> 4) << 4));
                uint32_t bf0[2] = { bw[0], bw[2] };
                uint32_t bf1[2] = { bw[1], bw[3] };
                float c1[2][2][4];
#pragma unroll
                for (int t = 0; t < 2; t++)
#pragma unroll
                    for (int jj = 0; jj < 2; jj++)
#pragma unroll
                        for (int q = 0; q < 4; q++) c1[t][jj][q] = 0.f;
#pragma unroll
                for (int t = 0; t < 2; t++) {
                    mma16816h(c1[t][0], ax[t], bf0);
                    mma16816h(c1[t][1], ax[t], bf1);
                }
#pragma unroll
                for (int t = 0; t < 2; t++)
#pragma unroll
                    for (int jj = 0; jj < 2; jj++)
#pragma unroll
                        for (int rh = 0; rh < 2; rh++) {
                            int row = wm + t * 16 + (lane >> 2) + rh * 8;
                            int col = wn + 16 * g + 8 * jj + (lane & 3) * 2;
                            float v0 = eluf(c1[t][jj][rh * 2 + 0] + sBiasAll[h * 128 + col]);
                            float v1 = eluf(c1[t][jj][rh * 2 + 1] + sBiasAll[h * 128 + col + 1]);
                            *(uint32_t*)(sA + (uint32_t)row * (TP * 2) + (uint32_t)col * 2) = p2h(v0, v1);
                        }
            }
        }
        // ---- prefetch next head's Xa/W into the other buffer (overlaps MMA2) ----
        if (h < NH - 1) {
            int row = tid >> 1, hb = tid & 1;
            CP_ASYNC16(xSd[pb ^ 1] + (uint32_t)row * 32 + hb * 16,
                       &g_xagg16[(size_t)(bm + row) * 64 + (h + 1) * 16 + hb * 8]);
            CP_ASYNC16(wSd[pb ^ 1] + (uint32_t)row * 32 + hb * 16,
                       &g_W1f[((h + 1) << 11) + (row << 4) + hb * 8]);
            CP_COMMIT();
            CP_WAIT1();    // B tile landed (prefetch group still in flight)
        } else {
            CP_WAIT0();
        }
        __syncthreads();   // sA stores + B visible
        // ---- MMA2: 8 k-steps ----
#pragma unroll
        for (int ks = 0; ks < 8; ks++) {
            int k0 = ks * 16;
            uint32_t ah[2][4], bh[16];
            {
                uint32_t rowb = (uint32_t)(wm + (lane & 15)) * (TP * 2)
                              + (uint32_t)(k0 + ((lane >> 4) << 3)) * 2;
                ldsm_x4(ah[0], aS + rowb);
                ldsm_x4(ah[1], aS + rowb + 16u * (TP * 2));
            }
#pragma unroll
            for (int g = 0; g < 4; g++) {
                uint32_t off = (uint32_t)(k0 + (lane & 15)) * (TP * 2)
                             + (uint32_t)(wn + 16 * g + ((lane >> 4) << 3)) * 2;
                ldsm_x4_t(&bh[4 * g], bS + off);
            }
#pragma unroll
            for (int t = 0; t < 2; t++)
#pragma unroll
                for (int j = 0; j < 8; j++)
                    mma16816h(acc[t][j], ah[t], &bh[2 * j]);
        }
    }

    // ---- epilogue: store h2, fused layer-2 attention scalars ----
    __syncthreads();
    if (tid < 128) { sPs[tid] = 0.f; sPd[tid] = 0.f; }
    __syncthreads();
#pragma unroll
    for (int t = 0; t < 2; t++)
#pragma unroll
        for (int rh = 0; rh < 2; rh++) {
            int rl = wm + t * 16 + (lane >> 2) + rh * 8;
            int row = bm + rl;
            float ps = 0.f, pd = 0.f;
#pragma unroll
            for (int j = 0; j < 8; j++) {
                float c0 = acc[t][j][rh * 2 + 0];
                float c1 = acc[t][j][rh * 2 + 1];
                int col = wn + 8 * j + (lane & 3) * 2;
                ps += c0 * sAv[col] + c1 * sAv[col + 1];
                pd += c0 * sDv[col] + c1 * sDv[col + 1];
                if (row < NN) {
                    *(float2*)&g_h2[(size_t)row * HIDC + col] = make_float2(c0, c1);
                }
            }
            ps += __shfl_xor_sync(0xffffffffu, ps, 1);
            ps += __shfl_xor_sync(0xffffffffu, ps, 2);
            pd += __shfl_xor_sync(0xffffffffu, pd, 1);
            pd += __shfl_xor_sync(0xffffffffu, pd, 2);
            if ((lane & 3) == 0) {
                atomicAdd(&sPs[rl], ps);
                atomicAdd(&sPd[rl], pd);
            }
        }
    __syncthreads();
    if (tid < 128) {
        int row = bm + tid;
        if (row < NN) { g_as2[row] = sPs[tid]; g_ad2[row] = sPd[tid]; }
    }
}

// ---------------- 10: layer-2 aggregation (warp per node) ----------------
__global__ void k_agg2(const float* __restrict__ b2) {
    int v = (blockIdx.x * blockDim.x + threadIdx.x) >> 5;
    int lane = threadIdx.x & 31;
    if (v >= NN) return;
    int e0 = g_rowoff[v], e1 = g_rowoff[v + 1];
    float ad = g_ad2[v];
    float z = 0.f;
    float4 acc = make_float4(0.f, 0.f, 0.f, 0.f);
    for (int e = e0; e < e1; e++) {
        int s = g_csrc[e];
        float w = fexp(lrelu(g_as2[s] + ad));
        z += w;
        float4 hv = *(const float4*)&g_h2[(size_t)s * HIDC + lane * 4];
        acc.x += w * hv.x; acc.y += w * hv.y; acc.z += w * hv.z; acc.w += w * hv.w;
    }
    float inv = 1.f / (z + 1e-16f);
    float4 bv = *(const float4*)&b2[lane * 4];
    float4 o;
    o.x = eluf(acc.x * inv + bv.x); o.y = eluf(acc.y * inv + bv.y);
    o.z = eluf(acc.z * inv + bv.z); o.w = eluf(acc.w * inv + bv.w);
    *(float4*)&g_act2[(size_t)v * HIDC + lane * 4] = o;
}

// ---------------- 11: pooled sums ----------------
#define POOL_NPB 64
__global__ __launch_bounds__(128) void k_pool(const int* __restrict__ batch, float* __restrict__ out) {
    int c = threadIdx.x;
    int n0 = blockIdx.x * POOL_NPB;
    int n1 = min(NN, n0 + POOL_NPB);
    float acc = 0.f;
    int gcur = -1, cnt = 0;
    for (int n = n0; n < n1; n++) {
        int g = batch[n];
        if (g != gcur) {
            if (gcur >= 0) {
                atomicAdd(&out[gcur * HIDC + c], acc);
                if (c == 0) atomicAdd(&g_cnt[gcur], (float)cnt);
            }
            acc = 0.f; cnt = 0; gcur = g;
        }
        acc += g_act2[(size_t)n * HIDC + c];
        cnt++;
    }
    if (gcur >= 0) {
        atomicAdd(&out[gcur * HIDC + c], acc);
        if (c == 0) atomicAdd(&g_cnt[gcur], (float)cnt);
    }
}

// ---------------- 12: divide by counts ----------------
__global__ void k_final(float* __restrict__ out) {
    int i = blockIdx.x * blockDim.x + threadIdx.x;
    if (i >= GG * HIDC) return;
    out[i] = out[i] / fmaxf(g_cnt[i >> 7], 1.f);
}

// ---------------- launch ----------------
extern "C" void kernel_launch(void* const* d_in, const int* in_sizes, int n_in,
                              void* d_out, int out_size) {
    const float* x      = (const float*)d_in[0];
    const int*   ei     = (const int*)  d_in[1];
    const int*   batch  = (const int*)  d_in[2];
    const float* W1     = (const float*)d_in[3];
    const float* a_src1 = (const float*)d_in[4];
    const float* a_dst1 = (const float*)d_in[5];
    const float* b1     = (const float*)d_in[6];
    const float* W2     = (const float*)d_in[7];
    const float* a_src2 = (const float*)d_in[8];
    const float* a_dst2 = (const float*)d_in[9];
    const float* b2     = (const float*)d_in[10];
    float* out = (float*)d_out;

    cudaFuncSetAttribute(k_fused_mma, cudaFuncAttributeMaxDynamicSharedMemorySize, FUSED_DYN_SMEM);

    int nblk = (NN + 127) / 128;
    int nscan = (NN + 1023) / 1024;   // 98

    k_prep<<<(NN * 12 + 255) / 256, 256>>>(out, x, W2, W1, a_src1, a_dst1);  // 0
    k_hist<<<(ETOT + 255) / 256, 256>>>(ei);                                 // 1
    k_scanA<<<nscan, 1024>>>();                                              // 2
    k_alpha1<<<(NN + 255) / 256, 256>>>();                                   // 3 (ncu window)
    k_scanB<<<1, 128>>>();                                                   // 4
    k_scanC<<<nscan, 1024>>>();                                              // 5
    k_scatter<<<(ETOT + 255) / 256, 256>>>(ei);                              // 6
    k_agg1<<<(NN + 255) / 256, 256>>>();                                     // 7
    k_fused_mma<<<nblk, 256, FUSED_DYN_SMEM>>>(b1, a_src2, a_dst2);          // 8
    k_agg2<<<(NN * 32 + 255) / 256, 256>>>(b2);                              // 9
    k_pool<<<(NN + POOL_NPB - 1) / POOL_NPB, 128>>>(batch, out);             // 10
    k_final<<<(GG * HIDC + 255) / 256, 256>>>(out);                          // 11
}